// round 1
// baseline (speedup 1.0000x reference)
#include <cuda_runtime.h>
#include <cuda_bf16.h>
#include <math.h>
#include <stdint.h>

// Problem constants
#define B_   1024
#define DIM_ 512
#define C_   1000
#define N_   8
#define CN_  8000
#define TOPK_ 400
#define WLAMBDA 0.3

// ---------------- scratch (device globals; no allocation allowed) ----------
__device__ float  g_xT[DIM_ * B_];          // 512 x 1024 (k-major x)
__device__ float  g_inv[CN_];               // 1/||proxies col||
__device__ float  g_sim[(size_t)B_ * CN_];  // 1024 x 8000
__device__ float  g_ccls[DIM_ * C_];        // 512 x 1000 (per-class center sums)
__device__ float  g_clog[(size_t)CN_ * C_]; // 8000 x 1000
__device__ double g_acc[2];                 // [0]=sum loss_classify, [1]=sum reg

// ---------------- zero accumulators ----------------------------------------
__global__ void zero_kernel() {
    if (threadIdx.x < 2) g_acc[threadIdx.x] = 0.0;
}

// ---------------- transpose x: (1024,512) -> (512,1024) ---------------------
__global__ void transpose_kernel(const float* __restrict__ x) {
    __shared__ float t[32][33];
    int bx = blockIdx.x * 32;  // along DIM
    int by = blockIdx.y * 32;  // along B
    int tx = threadIdx.x, ty = threadIdx.y;
    #pragma unroll
    for (int i = 0; i < 32; i += 8)
        t[ty + i][tx] = x[(size_t)(by + ty + i) * DIM_ + bx + tx];
    __syncthreads();
    #pragma unroll
    for (int i = 0; i < 32; i += 8)
        g_xT[(size_t)(bx + ty + i) * B_ + by + tx] = t[tx][ty + i];
}

// ---------------- column norms of proxies -----------------------------------
__global__ void colnorm_kernel(const float* __restrict__ proxies) {
    int j = blockIdx.x * blockDim.x + threadIdx.x;
    if (j >= CN_) return;
    float s = 0.f;
    #pragma unroll 8
    for (int d = 0; d < DIM_; d++) {
        float v = proxies[(size_t)d * CN_ + j];
        s += v * v;
    }
    g_inv[j] = 1.0f / fmaxf(sqrtf(s), 1e-12f);
}

// ---------------- per-class center sums: ccls[d,c] = sum_n centers[d, c*8+n] -
__global__ void ccls_kernel(const float* __restrict__ proxies) {
    int t = blockIdx.x * blockDim.x + threadIdx.x;
    if (t >= DIM_ * C_) return;
    int c = t % C_;
    int d = t / C_;
    size_t base = (size_t)d * CN_ + c * N_;
    float s = 0.f;
    #pragma unroll
    for (int n = 0; n < N_; n++)
        s += proxies[base + n] * g_inv[c * N_ + n];
    g_ccls[(size_t)d * C_ + c] = s;
}

// ---------------- shared SGEMM 128x128x8, 256 threads, 8x8 microtile --------
// mode 0: C=g_sim = (x @ proxies) * inv[col]      M=1024 N=8000 K=512
//         A=g_xT (lda=1024), B=proxies (ldb=8000)
// mode 1: C=g_clog = inv[row] * (proxies^T @ ccls) M=8000 N=1000 K=512
//         A=proxies (lda=8000), B=g_ccls (ldb=1000)
__global__ __launch_bounds__(256, 2) void gemm_kernel(int mode, const float* __restrict__ proxies) {
    const float* A; const float* Bm; float* Cm;
    int lda, ldb, M, N;
    bool colscale;
    if (mode == 0) {
        A = g_xT;   lda = B_;  Bm = proxies; ldb = CN_;
        Cm = g_sim; M = B_;    N = CN_;      colscale = true;
    } else {
        A = proxies; lda = CN_; Bm = g_ccls; ldb = C_;
        Cm = g_clog; M = CN_;   N = C_;      colscale = false;
    }
    const int K = DIM_;

    __shared__ float As[8][128];
    __shared__ float Bs[8][128];

    int tid = threadIdx.x;
    int bm = blockIdx.y * 128, bn = blockIdx.x * 128;

    float acc[8][8];
    #pragma unroll
    for (int i = 0; i < 8; i++)
        #pragma unroll
        for (int j = 0; j < 8; j++) acc[i][j] = 0.f;

    int r0 = (tid >> 4) * 4;   // 0..60
    int c0 = (tid & 15) * 4;   // 0..60

    for (int k0 = 0; k0 < K; k0 += 8) {
        #pragma unroll
        for (int e = 0; e < 4; e++) {
            int idx = tid + e * 256;
            int m = idx & 127, kk = idx >> 7;
            int gm = bm + m;
            As[kk][m] = (gm < M) ? A[(size_t)(k0 + kk) * lda + gm] : 0.f;
            int gn = bn + m;
            Bs[kk][m] = (gn < N) ? Bm[(size_t)(k0 + kk) * ldb + gn] : 0.f;
        }
        __syncthreads();
        #pragma unroll
        for (int kk = 0; kk < 8; kk++) {
            float4 a0 = *(const float4*)&As[kk][r0];
            float4 a1 = *(const float4*)&As[kk][r0 + 64];
            float4 b0 = *(const float4*)&Bs[kk][c0];
            float4 b1 = *(const float4*)&Bs[kk][c0 + 64];
            float av[8] = {a0.x, a0.y, a0.z, a0.w, a1.x, a1.y, a1.z, a1.w};
            float bv[8] = {b0.x, b0.y, b0.z, b0.w, b1.x, b1.y, b1.z, b1.w};
            #pragma unroll
            for (int i = 0; i < 8; i++)
                #pragma unroll
                for (int j = 0; j < 8; j++)
                    acc[i][j] += av[i] * bv[j];
        }
        __syncthreads();
    }

    #pragma unroll
    for (int i = 0; i < 8; i++) {
        int gm = bm + ((i < 4) ? (r0 + i) : (r0 + 60 + i));  // r0+i or r0+64+(i-4)
        if (gm >= M) continue;
        float rs = colscale ? 1.f : g_inv[gm];
        #pragma unroll
        for (int j = 0; j < 8; j++) {
            int gn = bn + ((j < 4) ? (c0 + j) : (c0 + 60 + j));
            if (gn >= N) continue;
            float s = colscale ? g_inv[gn] : rs;
            Cm[(size_t)gm * N + gn] = acc[i][j] * s;
        }
    }
}

// ---------------- per-row topk (radix select) + classification loss --------
__device__ __forceinline__ unsigned key_of(float v) {
    unsigned u = __float_as_uint(v);
    return (u & 0x80000000u) ? ~u : (u | 0x80000000u);
}

__global__ __launch_bounds__(256) void topk_loss_kernel(const int* __restrict__ target) {
    int b = blockIdx.x;
    const float* row = g_sim + (size_t)b * CN_;
    int tgt = target[b];
    int tid = threadIdx.x;

    __shared__ unsigned hist[2048];
    __shared__ unsigned csum[256];
    __shared__ float    cls[C_];
    __shared__ float    red[256];
    __shared__ unsigned sh_bin, sh_need;

    unsigned need = TOPK_;
    unsigned p = 0;
    const int shifts[3] = {21, 10, 0};

    for (int lvl = 0; lvl < 3; lvl++) {
        int shift = shifts[lvl];
        int nb = (lvl == 2) ? 1024 : 2048;

        for (int i = tid; i < nb; i += 256) hist[i] = 0;
        __syncthreads();

        for (int j = tid; j < CN_; j += 256) {
            float v = row[j] + (((j >> 3) == tgt) ? 1000.0f : 0.0f);
            unsigned k = key_of(v);
            bool ok = (lvl == 0) || ((k >> shifts[lvl - 1]) == p);
            if (ok) atomicAdd(&hist[(k >> shift) & (nb - 1)], 1u);
        }
        __syncthreads();

        // descending chunked scan to locate the bin holding the need-th largest
        unsigned s = 0;
        int base = nb - 8 * (tid + 1);
        if (base >= 0) {
            #pragma unroll
            for (int i = 7; i >= 0; i--) s += hist[base + i];
        }
        csum[tid] = s;
        __syncthreads();
        if (tid == 0) {
            unsigned cum = 0;
            int t;
            int nchunk = nb / 8;
            for (t = 0; t < nchunk; t++) {
                if (cum + csum[t] >= need) break;
                cum += csum[t];
            }
            int bb = nb - 8 * t - 1;
            for (;; bb--) {
                if (cum + hist[bb] >= need) break;
                cum += hist[bb];
            }
            sh_bin = (unsigned)bb;
            sh_need = need - cum;
        }
        __syncthreads();
        unsigned bin = sh_bin;
        need = sh_need;
        if (lvl == 0)      p = bin;
        else if (lvl == 1) p = (p << 11) | bin;
        else               p = (p << 10) | bin;
        __syncthreads();
    }
    unsigned T = p;  // exact key of the 400th-largest boosted value

    // class-bucketed sum over selected entries
    for (int c = tid; c < C_; c += 256) cls[c] = 0.f;
    __syncthreads();
    for (int j = tid; j < CN_; j += 256) {
        float v = row[j] + (((j >> 3) == tgt) ? 1000.0f : 0.0f);
        if (key_of(v) >= T) atomicAdd(&cls[j >> 3], row[j]);
    }
    __syncthreads();

    // masked softmax loss on class logits
    float lsum = 0.f;
    for (int c = tid; c < C_; c += 256) {
        float l = cls[c];
        if (l != 0.0f) lsum += expf(l);
    }
    red[tid] = lsum;
    __syncthreads();
    for (int s2 = 128; s2 > 0; s2 >>= 1) {
        if (tid < s2) red[tid] += red[tid + s2];
        __syncthreads();
    }
    if (tid == 0) {
        float lt = cls[tgt];
        float num = (lt != 0.0f) ? expf(lt) : 0.0f;
        float pr = num / (1e-8f + red[0]);
        float loss = -logf(pr + 1e-20f);
        atomicAdd(&g_acc[0], (double)loss);
    }
}

// ---------------- regularizer: per-row logsumexp over g_clog ----------------
__global__ __launch_bounds__(256) void lse_reg_kernel() {
    int row = blockIdx.x * 8 + (threadIdx.x >> 5);
    int lane = threadIdx.x & 31;
    const float* r = g_clog + (size_t)row * C_;

    float mx = -1e30f;
    for (int c = lane; c < C_; c += 32) mx = fmaxf(mx, r[c]);
    #pragma unroll
    for (int o = 16; o > 0; o >>= 1) mx = fmaxf(mx, __shfl_xor_sync(0xffffffffu, mx, o));

    float s = 0.f;
    for (int c = lane; c < C_; c += 32) s += expf(r[c] - mx);
    #pragma unroll
    for (int o = 16; o > 0; o >>= 1) s += __shfl_xor_sync(0xffffffffu, s, o);

    if (lane == 0) {
        int cl = row >> 3;
        float lse = mx + logf(s);
        float regj = lse - r[cl];
        atomicAdd(&g_acc[1], (double)regj);
    }
}

// ---------------- finalize ---------------------------------------------------
__global__ void finalize_kernel(float* out, int out_size) {
    double lc = g_acc[0] / (double)B_;
    double rg = g_acc[1] / (double)CN_;
    double tot = lc + WLAMBDA * rg;
    out[0] = (float)tot;
    if (out_size > 1) out[1] = (float)lc;
}

// ---------------- launch -----------------------------------------------------
extern "C" void kernel_launch(void* const* d_in, const int* in_sizes, int n_in,
                              void* d_out, int out_size) {
    const float* x       = (const float*)d_in[0];
    const float* proxies = (const float*)d_in[1];
    const int*   target  = (const int*)d_in[2];
    float* out = (float*)d_out;

    zero_kernel<<<1, 32>>>();
    transpose_kernel<<<dim3(DIM_ / 32, B_ / 32), dim3(32, 8)>>>(x);
    colnorm_kernel<<<(CN_ + 255) / 256, 256>>>(proxies);
    ccls_kernel<<<(DIM_ * C_ + 255) / 256, 256>>>(proxies);

    // sim = x @ centers (scaled by inv[col])
    gemm_kernel<<<dim3((CN_ + 127) / 128, (B_ + 127) / 128), 256>>>(0, proxies);
    // centers_logits = centers^T @ centers_cls (scaled by inv[row])
    gemm_kernel<<<dim3((C_ + 127) / 128, (CN_ + 127) / 128), 256>>>(1, proxies);

    topk_loss_kernel<<<B_, 256>>>(target);
    lse_reg_kernel<<<CN_ / 8, 256>>>();

    finalize_kernel<<<1, 1>>>(out, out_size);
}

// round 3
// speedup vs baseline: 1.9064x; 1.9064x over previous
#include <cuda_runtime.h>
#include <math.h>
#include <stdint.h>

// ---------------- problem constants ----------------------------------------
#define B_    1024
#define DIM_  512
#define C_    1000
#define N_    8
#define CN_   8000
#define CNP_  8064      // CN padded to multiple of 128
#define CP_   1024      // C padded to multiple of 128
#define NEED_ 392       // topk(400) = 8 always-selected positives + top-392 others
#define WLAMBDA 0.3

// ---------------- scratch (device globals) ----------------------------------
__device__ float  g_inv[CN_];
__device__ float  g_xr[(size_t)B_ * DIM_];      // tf32-rounded x
__device__ float  g_pT[(size_t)CNP_ * DIM_];    // normalized centers^T (tf32-rounded)
__device__ float  g_cclsT[(size_t)CP_ * DIM_];  // per-class center sums^T (tf32-rounded)
__device__ float  g_sim[(size_t)B_ * CN_];
__device__ float  g_clog[(size_t)CN_ * C_];
__device__ double g_acc[2];

// ---------------- helpers ----------------------------------------------------
__device__ __forceinline__ uint32_t smem_u32(const void* p) {
    uint32_t a;
    asm("{ .reg .u64 t; cvta.to.shared.u64 t, %1; cvt.u32.u64 %0, t; }" : "=r"(a) : "l"(p));
    return a;
}
__device__ __forceinline__ float tf32r(float f) {
    uint32_t r;
    asm("cvt.rna.tf32.f32 %0, %1;" : "=r"(r) : "f"(f));
    return __uint_as_float(r);
}
__device__ __forceinline__ void cpa16(uint32_t dst, const void* src) {
    uint64_t g = __cvta_generic_to_global(src);
    asm volatile("cp.async.cg.shared.global [%0], [%1], 16;" :: "r"(dst), "l"(g));
}
#define CP_COMMIT() asm volatile("cp.async.commit_group;" ::: "memory")

__device__ __forceinline__ void mma_tf32(float* c, const uint32_t* a, const uint32_t* b) {
    asm volatile(
        "mma.sync.aligned.m16n8k8.row.col.f32.tf32.tf32.f32 "
        "{%0,%1,%2,%3}, {%4,%5,%6,%7}, {%8,%9}, {%0,%1,%2,%3};"
        : "+f"(c[0]), "+f"(c[1]), "+f"(c[2]), "+f"(c[3])
        : "r"(a[0]), "r"(a[1]), "r"(a[2]), "r"(a[3]), "r"(b[0]), "r"(b[1]));
}

// ---------------- small prep kernels ----------------------------------------
__global__ void zero_kernel() {
    if (threadIdx.x < 2) g_acc[threadIdx.x] = 0.0;
}

__global__ void roundx_kernel(const float* __restrict__ x) {
    int i = blockIdx.x * 256 + threadIdx.x;
    g_xr[i] = tf32r(x[i]);
}

__global__ void colnorm_kernel(const float* __restrict__ proxies) {
    int j = blockIdx.x * blockDim.x + threadIdx.x;
    if (j >= CN_) return;
    float s = 0.f;
    #pragma unroll 8
    for (int d = 0; d < DIM_; d++) {
        float v = proxies[(size_t)d * CN_ + j];
        s += v * v;
    }
    g_inv[j] = 1.0f / fmaxf(sqrtf(s), 1e-12f);
}

// g_pT[j][d] = round_tf32(proxies[d][j] * inv[j]), rows padded with zeros
__global__ void transpose_norm_kernel(const float* __restrict__ proxies) {
    __shared__ float t[32][33];
    int j0 = blockIdx.x * 32, d0 = blockIdx.y * 32;
    int tx = threadIdx.x, ty = threadIdx.y;
    #pragma unroll
    for (int i = 0; i < 32; i += 8) {
        int d = d0 + ty + i, j = j0 + tx;
        t[ty + i][tx] = (j < CN_) ? proxies[(size_t)d * CN_ + j] : 0.f;
    }
    __syncthreads();
    #pragma unroll
    for (int i = 0; i < 32; i += 8) {
        int j = j0 + ty + i, d = d0 + tx;
        if (j < CNP_) {
            float s = (j < CN_) ? g_inv[j] : 0.f;
            g_pT[(size_t)j * DIM_ + d] = tf32r(t[tx][ty + i] * s);
        }
    }
}

// g_cclsT[c][d] = round_tf32(sum_n g_pT[c*8+n][d]), rows padded zero
__global__ void cclsT_kernel() {
    int idx = blockIdx.x * blockDim.x + threadIdx.x;
    if (idx >= CP_ * DIM_) return;
    int c = idx >> 9, d = idx & 511;
    float s = 0.f;
    if (c < C_) {
        #pragma unroll
        for (int n = 0; n < N_; n++)
            s += g_pT[(size_t)(c * N_ + n) * DIM_ + d];
    }
    g_cclsT[idx] = tf32r(s);
}

// ---------------- tf32 mma.sync GEMM ----------------------------------------
// D[m][n] = sum_k A[m][k] * B[n][k]; both operands K-contiguous, K=512.
// mode 0: A=g_xr (1024x512),  B=g_pT (8064x512)   -> g_sim  (1024x8000)
// mode 1: A=g_pT (8064x512),  B=g_cclsT (1024x512) -> g_clog (8000x1000)
#define BK 32
#define NCHUNK (DIM_ / BK)    // 16
#define LDSS 36               // padded row stride (floats)
#define STAGE_FLOATS (256 * LDSS)  // 9216
#define DYN_SMEM (4 * STAGE_FLOATS * 4)  // 147456 B

__global__ void __launch_bounds__(256) gemm_tc(int mode) {
    extern __shared__ float sh[];
    const float *A, *Bm;
    float* Cm;
    int Mrows, Ncols;
    if (mode == 0) { A = g_xr; Bm = g_pT;    Cm = g_sim;  Mrows = B_;  Ncols = CN_; }
    else           { A = g_pT; Bm = g_cclsT; Cm = g_clog; Mrows = CN_; Ncols = C_;  }

    int tid = threadIdx.x, wid = tid >> 5, lane = tid & 31;
    int bm = blockIdx.y * 128, bn = blockIdx.x * 128;
    uint32_t sb = smem_u32(sh);

    auto load_stage = [&](int ch, int s) {
        #pragma unroll
        for (int e = 0; e < 8; e++) {
            int lin = e * 256 + tid;
            int row = (lin >> 3) & 127, q = lin & 7;
            bool isB = lin >= 1024;
            const float* src = isB ? (Bm + (size_t)(bn + row) * DIM_ + ch * BK + q * 4)
                                   : (A  + (size_t)(bm + row) * DIM_ + ch * BK + q * 4);
            uint32_t dst = sb + ((uint32_t)(s * STAGE_FLOATS + (isB ? 128 * LDSS : 0) + row * LDSS + q * 4) << 2);
            cpa16(dst, src);
        }
        CP_COMMIT();
    };

    load_stage(0, 0);
    load_stage(1, 1);
    load_stage(2, 2);

    int wm = (wid >> 2) * 64, wn = (wid & 3) * 32;
    int lr = lane >> 2, lc = lane & 3;

    float c[4][4][4];
    #pragma unroll
    for (int mt = 0; mt < 4; mt++)
        #pragma unroll
        for (int nt = 0; nt < 4; nt++)
            #pragma unroll
            for (int i = 0; i < 4; i++) c[mt][nt][i] = 0.f;

    for (int ch = 0; ch < NCHUNK; ch++) {
        if (ch < 14)       asm volatile("cp.async.wait_group 2;" ::: "memory");
        else if (ch == 14) asm volatile("cp.async.wait_group 1;" ::: "memory");
        else               asm volatile("cp.async.wait_group 0;" ::: "memory");
        __syncthreads();

        if (ch + 3 < NCHUNK) load_stage(ch + 3, (ch + 3) & 3);

        const float* As = sh + (ch & 3) * STAGE_FLOATS;
        const float* Bs = As + 128 * LDSS;

        #pragma unroll
        for (int ks = 0; ks < 4; ks++) {
            int k0 = ks * 8;
            uint32_t a[4][4], b[4][2];
            #pragma unroll
            for (int mt = 0; mt < 4; mt++) {
                int r = wm + mt * 16 + lr;
                a[mt][0] = __float_as_uint(As[r * LDSS + k0 + lc]);
                a[mt][1] = __float_as_uint(As[(r + 8) * LDSS + k0 + lc]);
                a[mt][2] = __float_as_uint(As[r * LDSS + k0 + 4 + lc]);
                a[mt][3] = __float_as_uint(As[(r + 8) * LDSS + k0 + 4 + lc]);
            }
            #pragma unroll
            for (int nt = 0; nt < 4; nt++) {
                int cc = wn + nt * 8 + lr;
                b[nt][0] = __float_as_uint(Bs[cc * LDSS + k0 + lc]);
                b[nt][1] = __float_as_uint(Bs[cc * LDSS + k0 + 4 + lc]);
            }
            #pragma unroll
            for (int mt = 0; mt < 4; mt++)
                #pragma unroll
                for (int nt = 0; nt < 4; nt++)
                    mma_tf32(c[mt][nt], a[mt], b[nt]);
        }
    }

    // epilogue: float2 stores, guarded
    #pragma unroll
    for (int mt = 0; mt < 4; mt++) {
        int row = bm + wm + mt * 16 + lr;
        #pragma unroll
        for (int nt = 0; nt < 4; nt++) {
            int col = bn + wn + nt * 8 + lc * 2;
            if (col < Ncols) {
                if (row < Mrows)
                    *(float2*)(Cm + (size_t)row * Ncols + col) = make_float2(c[mt][nt][0], c[mt][nt][1]);
                if (row + 8 < Mrows)
                    *(float2*)(Cm + (size_t)(row + 8) * Ncols + col) = make_float2(c[mt][nt][2], c[mt][nt][3]);
            }
        }
    }
}

// ---------------- topk (SMEM-cached radix select) + classification loss -----
__device__ __forceinline__ unsigned key_of(float v) {
    unsigned u = __float_as_uint(v);
    return (u & 0x80000000u) ? ~u : (u | 0x80000000u);
}
__device__ __forceinline__ float key_inv(unsigned k) {
    unsigned u = (k & 0x80000000u) ? (k & 0x7FFFFFFFu) : ~k;
    return __uint_as_float(u);
}

__global__ void __launch_bounds__(256) topk_loss_kernel(const int* __restrict__ target) {
    int b = blockIdx.x;
    const float* row = g_sim + (size_t)b * CN_;
    int tgt = target[b];
    int tid = threadIdx.x;

    __shared__ unsigned keys[CN_];
    __shared__ unsigned hist[2048];
    __shared__ unsigned csum[256];
    __shared__ float    cls[C_];
    __shared__ float    red[256];
    __shared__ float    s_pos;
    __shared__ unsigned sh_bin, sh_need;

    for (int c = tid; c < C_; c += 256) cls[c] = 0.f;
    if (tid == 0) s_pos = 0.f;
    __syncthreads();

    // one global pass: cache keys (positives excluded via key 0, summed separately;
    // the 8 positives are always in the top-400 because of the +1000 boost)
    for (int j = tid; j < CN_; j += 256) {
        float v = row[j];
        if ((j >> 3) == tgt) {
            atomicAdd(&s_pos, v);
            keys[j] = 0u;
        } else {
            keys[j] = key_of(v);
        }
    }
    __syncthreads();

    unsigned need = NEED_;
    unsigned p = 0;
    const int shifts[3] = {21, 10, 0};

    for (int lvl = 0; lvl < 3; lvl++) {
        int shift = shifts[lvl];
        int nb = (lvl == 2) ? 1024 : 2048;

        for (int i = tid; i < nb; i += 256) hist[i] = 0;
        __syncthreads();

        for (int j = tid; j < CN_; j += 256) {
            unsigned k = keys[j];
            bool ok = (lvl == 0) || ((k >> shifts[lvl - 1]) == p);
            if (ok) atomicAdd(&hist[(k >> shift) & (nb - 1)], 1u);
        }
        __syncthreads();

        unsigned s = 0;
        int base = nb - 8 * (tid + 1);
        if (base >= 0) {
            #pragma unroll
            for (int i = 7; i >= 0; i--) s += hist[base + i];
        }
        csum[tid] = s;
        __syncthreads();
        if (tid == 0) {
            unsigned cum = 0;
            int t;
            int nchunk = nb / 8;
            for (t = 0; t < nchunk; t++) {
                if (cum + csum[t] >= need) break;
                cum += csum[t];
            }
            int bb = nb - 8 * t - 1;
            for (;; bb--) {
                if (cum + hist[bb] >= need) break;
                cum += hist[bb];
            }
            sh_bin = (unsigned)bb;
            sh_need = need - cum;
        }
        __syncthreads();
        unsigned bin = sh_bin;
        need = sh_need;
        if (lvl == 0)      p = bin;
        else if (lvl == 1) p = (p << 11) | bin;
        else               p = (p << 10) | bin;
        __syncthreads();
    }
    unsigned T = p;  // key of 392nd-largest non-positive

    for (int j = tid; j < CN_; j += 256) {
        unsigned k = keys[j];
        if (k >= T) atomicAdd(&cls[j >> 3], key_inv(k));
    }
    __syncthreads();
    if (tid == 0) cls[tgt] += s_pos;
    __syncthreads();

    float lsum = 0.f;
    for (int c = tid; c < C_; c += 256) {
        float l = cls[c];
        if (l != 0.0f) lsum += expf(l);
    }
    red[tid] = lsum;
    __syncthreads();
    for (int s2 = 128; s2 > 0; s2 >>= 1) {
        if (tid < s2) red[tid] += red[tid + s2];
        __syncthreads();
    }
    if (tid == 0) {
        float lt = cls[tgt];
        float num = (lt != 0.0f) ? expf(lt) : 0.0f;
        float pr = num / (1e-8f + red[0]);
        float loss = -logf(pr + 1e-20f);
        atomicAdd(&g_acc[0], (double)loss);
    }
}

// ---------------- regularizer: per-row logsumexp over g_clog ----------------
__global__ void __launch_bounds__(256) lse_reg_kernel() {
    int row = blockIdx.x * 8 + (threadIdx.x >> 5);
    int lane = threadIdx.x & 31;
    const float* r = g_clog + (size_t)row * C_;

    float mx = -1e30f;
    for (int c = lane; c < C_; c += 32) mx = fmaxf(mx, r[c]);
    #pragma unroll
    for (int o = 16; o > 0; o >>= 1) mx = fmaxf(mx, __shfl_xor_sync(0xffffffffu, mx, o));

    float s = 0.f;
    for (int c = lane; c < C_; c += 32) s += expf(r[c] - mx);
    #pragma unroll
    for (int o = 16; o > 0; o >>= 1) s += __shfl_xor_sync(0xffffffffu, s, o);

    if (lane == 0) {
        int cl = row >> 3;
        float lse = mx + logf(s);
        atomicAdd(&g_acc[1], (double)(lse - r[cl]));
    }
}

// ---------------- finalize ---------------------------------------------------
__global__ void finalize_kernel(float* out, int out_size) {
    double lc = g_acc[0] / (double)B_;
    double rg = g_acc[1] / (double)CN_;
    out[0] = (float)(lc + WLAMBDA * rg);
    if (out_size > 1) out[1] = (float)lc;
}

// ---------------- launch -----------------------------------------------------
extern "C" void kernel_launch(void* const* d_in, const int* in_sizes, int n_in,
                              void* d_out, int out_size) {
    const float* x       = (const float*)d_in[0];
    const float* proxies = (const float*)d_in[1];
    const int*   target  = (const int*)d_in[2];
    float* out = (float*)d_out;

    static int attr_set = 0;
    if (!attr_set) {
        cudaFuncSetAttribute(gemm_tc, cudaFuncAttributeMaxDynamicSharedMemorySize, DYN_SMEM);
        attr_set = 1;
    }

    zero_kernel<<<1, 32>>>();
    roundx_kernel<<<(B_ * DIM_) / 256, 256>>>(x);
    colnorm_kernel<<<(CN_ + 255) / 256, 256>>>(proxies);
    transpose_norm_kernel<<<dim3(CNP_ / 32, DIM_ / 32), dim3(32, 8)>>>(proxies);
    cclsT_kernel<<<(CP_ * DIM_ + 255) / 256, 256>>>();

    // sim = x @ centers           : grid (63 N-tiles, 8 M-tiles)
    gemm_tc<<<dim3(63, 8), 256, DYN_SMEM>>>(0);
    // centers_logits = centers^T @ centers_cls : grid (8 N-tiles, 63 M-tiles)
    gemm_tc<<<dim3(8, 63), 256, DYN_SMEM>>>(1);

    topk_loss_kernel<<<B_, 256>>>(target);
    lse_reg_kernel<<<CN_ / 8, 256>>>();

    finalize_kernel<<<1, 1>>>(out, out_size);
}

// round 4
// speedup vs baseline: 2.5161x; 1.3198x over previous
#include <cuda_runtime.h>
#include <math.h>
#include <stdint.h>

// ---------------- problem constants ----------------------------------------
#define B_    1024
#define DIM_  512
#define C_    1000
#define N_    8
#define CN_   8000
#define CNP_  8064      // CN padded to multiple of 128 (and 16)
#define CP_   1024      // C padded to multiple of 128
#define NEED_ 392       // topk(400) = 8 always-selected positives + top-392 others
#define WLAMBDA 0.3

// ---------------- scratch (device globals) ----------------------------------
// Fragment-major layouts (see gemm):
//  A-layout: float4 chunks [G=rows/16][ksG=K/8][q(8)][lc(4)],
//            chunk = (A[16G+q][8ksG+lc], A[16G+q+8][8ksG+lc],
//                     A[16G+q][8ksG+lc+4], A[16G+q+8][8ksG+lc+4])
//  B-layout: 16B chunks  [GB=cols/8][ksG][qB(8)][p(2)],
//            chunk = (B[8GB+qB][8ksG+2p],   B[8GB+qB][8ksG+2p+4],
//                     B[8GB+qB][8ksG+2p+1], B[8GB+qB][8ksG+2p+5])
__device__ float4 g_xrA[(size_t)(B_ / 16) * 64 * 8 * 4];     // x, A-layout
__device__ float4 g_pTA[(size_t)(CNP_ / 16) * 64 * 8 * 4];   // centers^T, A-layout
__device__ float4 g_pTB[(size_t)(CNP_ / 8) * 64 * 8 * 2];    // centers^T, B-layout
__device__ float4 g_ccB[(size_t)(CP_ / 8) * 64 * 8 * 2];     // class sums^T, B-layout
__device__ float  g_sim[(size_t)B_ * CN_];
__device__ float  g_clog[(size_t)CN_ * C_];
__device__ double g_acc[2];

// ---------------- helpers ----------------------------------------------------
__device__ __forceinline__ float tf32r(float f) {
    uint32_t r;
    asm("cvt.rna.tf32.f32 %0, %1;" : "=r"(r) : "f"(f));
    return __uint_as_float(r);
}
__device__ __forceinline__ uint32_t smem_u32(const void* p) {
    uint32_t a;
    asm("{ .reg .u64 t; cvta.to.shared.u64 t, %1; cvt.u32.u64 %0, t; }" : "=r"(a) : "l"(p));
    return a;
}
__device__ __forceinline__ void cpa16(uint32_t dst, const void* src) {
    uint64_t g = __cvta_generic_to_global(src);
    asm volatile("cp.async.cg.shared.global [%0], [%1], 16;" :: "r"(dst), "l"(g));
}
#define CP_COMMIT() asm volatile("cp.async.commit_group;" ::: "memory")

__device__ __forceinline__ void mma_tf32(float* c, const uint32_t* a, const uint32_t* b) {
    asm volatile(
        "mma.sync.aligned.m16n8k8.row.col.f32.tf32.tf32.f32 "
        "{%0,%1,%2,%3}, {%4,%5,%6,%7}, {%8,%9}, {%0,%1,%2,%3};"
        : "+f"(c[0]), "+f"(c[1]), "+f"(c[2]), "+f"(c[3])
        : "r"(a[0]), "r"(a[1]), "r"(a[2]), "r"(a[3]), "r"(b[0]), "r"(b[1]));
}

// ---------------- prep: x -> A-layout (tf32-rounded); block 0 zeroes g_acc ---
__global__ void __launch_bounds__(256) prep_x(const float* __restrict__ x) {
    __shared__ float xs[16][516];
    int g = blockIdx.x, tid = threadIdx.x;
    if (g == 0 && tid < 2) g_acc[tid] = 0.0;

    const float4* x4 = (const float4*)x;
    #pragma unroll
    for (int e = 0; e < 8; e++) {
        int lin = e * 256 + tid;          // 2048 float4s
        int row = lin >> 7, kf = lin & 127;
        float4 v = x4[(size_t)(g * 16 + row) * 128 + kf];
        xs[row][kf * 4 + 0] = v.x; xs[row][kf * 4 + 1] = v.y;
        xs[row][kf * 4 + 2] = v.z; xs[row][kf * 4 + 3] = v.w;
    }
    __syncthreads();
    #pragma unroll
    for (int e = 0; e < 8; e++) {
        int lin = e * 256 + tid;          // 2048 output float4s
        int ksG = lin >> 5, q = (lin >> 2) & 7, lc = lin & 3;
        int k = ksG * 8 + lc;
        float4 o;
        o.x = tf32r(xs[q][k]);     o.y = tf32r(xs[q + 8][k]);
        o.z = tf32r(xs[q][k + 4]); o.w = tf32r(xs[q + 8][k + 4]);
        g_xrA[((size_t)g * 64 + ksG) * 32 + q * 4 + lc] = o;
    }
}

// ---------------- prep: proxies -> norms, pTA, pTB, ccB ----------------------
__global__ void __launch_bounds__(256) prep_prox(const float* __restrict__ proxies) {
    __shared__ float red[8][32];
    __shared__ float sinv[32];
    int j0 = blockIdx.x * 32, tid = threadIdx.x;
    int jj = tid & 31, ds = tid >> 5;

    // pass 1: column sumsq
    float acc = 0.f;
    for (int d = ds; d < DIM_; d += 8) {
        float v = proxies[(size_t)d * CN_ + j0 + jj];
        acc += v * v;
    }
    red[ds][jj] = acc;
    __syncthreads();
    if (ds == 0) {
        float s = 0.f;
        #pragma unroll
        for (int i = 0; i < 8; i++) s += red[i][jj];
        sinv[jj] = 1.0f / fmaxf(sqrtf(s), 1e-12f);
    }
    __syncthreads();

    // pass 2a: g_pTA (A-layout rows = proxy columns, k = d)
    #pragma unroll
    for (int e = 0; e < 16; e++) {
        int lin = e * 256 + tid;          // 4096
        int gl = lin >> 11, ksG = (lin >> 5) & 63, q = (lin >> 2) & 7, lc = lin & 3;
        int jA = j0 + gl * 16 + q;
        int d = ksG * 8 + lc;
        float4 o;
        o.x = tf32r(proxies[(size_t)d * CN_ + jA] * sinv[jA - j0]);
        o.y = tf32r(proxies[(size_t)d * CN_ + jA + 8] * sinv[jA + 8 - j0]);
        o.z = tf32r(proxies[(size_t)(d + 4) * CN_ + jA] * sinv[jA - j0]);
        o.w = tf32r(proxies[(size_t)(d + 4) * CN_ + jA + 8] * sinv[jA + 8 - j0]);
        g_pTA[((size_t)(j0 / 16 + gl) * 64 + ksG) * 32 + q * 4 + lc] = o;
    }

    // pass 2b: g_pTB (B-layout)
    #pragma unroll
    for (int e = 0; e < 16; e++) {
        int lin = e * 256 + tid;          // 4096
        int glB = lin >> 10, ksG = (lin >> 4) & 63, qB = (lin >> 1) & 7, p = lin & 1;
        int j = j0 + glB * 8 + qB;
        int k0 = ksG * 8 + 2 * p;
        float iv = sinv[j - j0];
        float4 o;
        o.x = tf32r(proxies[(size_t)k0 * CN_ + j] * iv);
        o.y = tf32r(proxies[(size_t)(k0 + 4) * CN_ + j] * iv);
        o.z = tf32r(proxies[(size_t)(k0 + 1) * CN_ + j] * iv);
        o.w = tf32r(proxies[(size_t)(k0 + 5) * CN_ + j] * iv);
        g_pTB[((size_t)(j0 / 8 + glB) * 64 + ksG) * 16 + qB * 2 + p] = o;
    }

    // pass 2c: g_ccB class sums (4 classes per block), B-layout
    #pragma unroll
    for (int e = 0; e < 2; e++) {
        int lin = e * 256 + tid;          // 512
        int cl = lin >> 7, ksG = (lin >> 1) & 63, p = lin & 1;
        int c = j0 / 8 + cl;
        int gB = c >> 3, qB = c & 7;
        int k0 = ksG * 8 + 2 * p;
        float s0 = 0.f, s1 = 0.f, s2 = 0.f, s3 = 0.f;
        #pragma unroll
        for (int n = 0; n < 8; n++) {
            int j = c * 8 + n;
            float iv = sinv[j - j0];
            s0 += proxies[(size_t)k0 * CN_ + j] * iv;
            s1 += proxies[(size_t)(k0 + 4) * CN_ + j] * iv;
            s2 += proxies[(size_t)(k0 + 1) * CN_ + j] * iv;
            s3 += proxies[(size_t)(k0 + 5) * CN_ + j] * iv;
        }
        float4 o = make_float4(tf32r(s0), tf32r(s1), tf32r(s2), tf32r(s3));
        g_ccB[((size_t)gB * 64 + ksG) * 16 + qB * 2 + p] = o;
    }
}

// ---------------- merged tf32 mma.sync GEMM ---------------------------------
// mode 0 (bid<504):  g_sim  = g_xrA @ g_pTB^T   (M=1024, N=8000)
// mode 1 (bid>=504): g_clog = g_pTA @ g_ccB^T   (M=8000, N=1000)
#define NCHUNK 16
#define STG 32768           // bytes per stage: A 16KB + B 16KB
#define DYN_SMEM (4 * STG)  // 131072

__global__ void __launch_bounds__(256) gemm_all() {
    extern __shared__ char sh[];
    int bid = blockIdx.x;
    const float4 *Ag, *Bg;
    float* Cm;
    int bm, bn, Mrows, Ncols;
    if (bid < 504) {
        Ag = g_xrA; Bg = g_pTB; Cm = g_sim;
        bn = (bid % 63) * 128; bm = (bid / 63) * 128;
        Mrows = B_; Ncols = CN_;
    } else {
        int b2 = bid - 504;
        Ag = g_pTA; Bg = g_ccB; Cm = g_clog;
        bn = (b2 & 7) * 128; bm = (b2 >> 3) * 128;
        Mrows = CN_; Ncols = C_;
    }
    int tid = threadIdx.x, wid = tid >> 5, lane = tid & 31;
    int lr = lane >> 2, lc4 = lane & 3;
    uint32_t sb = smem_u32(sh);
    int GA0 = bm / 16, GB0 = bn / 8;

    auto load_stage = [&](int ch, int s) {
        uint32_t stage = sb + (uint32_t)s * STG;
        #pragma unroll
        for (int e = 0; e < 8; e++) {
            int lin = e * 256 + tid;
            if (lin < 1024) {
                // A: [ks][g][q][lc] float4 (linear = lin)
                int ks = lin >> 8, g = (lin >> 5) & 7, q = (lin >> 2) & 7, lc = lin & 3;
                cpa16(stage + (uint32_t)lin * 16,
                      Ag + ((size_t)(GA0 + g) * 64 + ch * 4 + ks) * 32 + q * 4 + lc);
            } else {
                int l2 = lin - 1024;
                // B: [ks][gB][qB][p] 16B (linear = l2)
                int ks = l2 >> 8, gB = (l2 >> 4) & 15, qB = (l2 >> 1) & 7, p = l2 & 1;
                cpa16(stage + 16384u + (uint32_t)l2 * 16,
                      Bg + ((size_t)(GB0 + gB) * 64 + ch * 4 + ks) * 16 + qB * 2 + p);
            }
        }
        CP_COMMIT();
    };

    load_stage(0, 0);
    load_stage(1, 1);
    load_stage(2, 2);

    int ga = (wid >> 2) * 4;   // A group base (wm/16)
    int gb = (wid & 3) * 4;    // B group base (wn/8)

    float c[4][4][4];
    #pragma unroll
    for (int mt = 0; mt < 4; mt++)
        #pragma unroll
        for (int nt = 0; nt < 4; nt++)
            #pragma unroll
            for (int i = 0; i < 4; i++) c[mt][nt][i] = 0.f;

    for (int ch = 0; ch < NCHUNK; ch++) {
        if (ch < NCHUNK - 2)       asm volatile("cp.async.wait_group 2;" ::: "memory");
        else if (ch == NCHUNK - 2) asm volatile("cp.async.wait_group 1;" ::: "memory");
        else                       asm volatile("cp.async.wait_group 0;" ::: "memory");
        __syncthreads();

        if (ch + 3 < NCHUNK) load_stage(ch + 3, (ch + 3) & 3);

        const float4* As = (const float4*)(sh + (ch & 3) * STG);
        const float2* Bs = (const float2*)(sh + (ch & 3) * STG + 16384);

        #pragma unroll
        for (int ks = 0; ks < 4; ks++) {
            uint32_t a[4][4], b[4][2];
            #pragma unroll
            for (int mt = 0; mt < 4; mt++) {
                float4 v = As[((ks * 8 + ga + mt) * 8 + lr) * 4 + lc4];
                a[mt][0] = __float_as_uint(v.x); a[mt][1] = __float_as_uint(v.y);
                a[mt][2] = __float_as_uint(v.z); a[mt][3] = __float_as_uint(v.w);
            }
            #pragma unroll
            for (int nt = 0; nt < 4; nt++) {
                float2 v = Bs[((ks * 16 + gb + nt) * 8 + lr) * 4 + lc4];
                b[nt][0] = __float_as_uint(v.x); b[nt][1] = __float_as_uint(v.y);
            }
            #pragma unroll
            for (int mt = 0; mt < 4; mt++)
                #pragma unroll
                for (int nt = 0; nt < 4; nt++)
                    mma_tf32(c[mt][nt], a[mt], b[nt]);
        }
    }

    int wm = (wid >> 2) * 64, wn = (wid & 3) * 32;
    #pragma unroll
    for (int mt = 0; mt < 4; mt++) {
        int row = bm + wm + mt * 16 + lr;
        #pragma unroll
        for (int nt = 0; nt < 4; nt++) {
            int col = bn + wn + nt * 8 + lc4 * 2;
            if (col < Ncols) {
                if (row < Mrows)
                    *(float2*)(Cm + (size_t)row * Ncols + col) = make_float2(c[mt][nt][0], c[mt][nt][1]);
                if (row + 8 < Mrows)
                    *(float2*)(Cm + (size_t)(row + 8) * Ncols + col) = make_float2(c[mt][nt][2], c[mt][nt][3]);
            }
        }
    }
}

// ---------------- topk (radix select, parallel scans) + class loss ----------
__device__ __forceinline__ unsigned key_of(float v) {
    unsigned u = __float_as_uint(v);
    return (u & 0x80000000u) ? ~u : (u | 0x80000000u);
}
__device__ __forceinline__ float key_inv(unsigned k) {
    unsigned u = (k & 0x80000000u) ? (k & 0x7FFFFFFFu) : ~k;
    return __uint_as_float(u);
}

__global__ void __launch_bounds__(256) topk_loss_kernel(const int* __restrict__ target) {
    int b = blockIdx.x;
    const float* row = g_sim + (size_t)b * CN_;
    int tgt = target[b];
    int tid = threadIdx.x;

    __shared__ unsigned keys[CN_];
    __shared__ unsigned hist[2048];
    __shared__ unsigned sfx[256];
    __shared__ float    cls[C_];
    __shared__ float    red[256];
    __shared__ float    s_pos;
    __shared__ unsigned sh_bin, sh_need;

    for (int c = tid; c < C_; c += 256) cls[c] = 0.f;
    for (int i = tid; i < 2048; i += 256) hist[i] = 0;
    if (tid == 0) s_pos = 0.f;
    __syncthreads();

    // one global pass: cache keys + level-0 histogram.
    // positives (always in top-400 via the +1000 boost) get key 0 and are summed aside.
    for (int j = tid; j < CN_; j += 256) {
        float v = row[j];
        if ((j >> 3) == tgt) {
            atomicAdd(&s_pos, v);
            keys[j] = 0u;
        } else {
            unsigned k = key_of(v);
            keys[j] = k;
            atomicAdd(&hist[k >> 21], 1u);
        }
    }
    __syncthreads();

    unsigned need = NEED_;
    unsigned p = 0;
    const int shifts[3] = {21, 10, 0};

    for (int lvl = 0; lvl < 3; lvl++) {
        int nb = (lvl == 2) ? 1024 : 2048;
        int nch = nb >> 3;

        if (lvl > 0) {
            for (int i = tid; i < nb; i += 256) hist[i] = 0;
            __syncthreads();
            int shift = shifts[lvl], pshift = shifts[lvl - 1];
            for (int j = tid; j < CN_; j += 256) {
                unsigned k = keys[j];
                if ((k >> pshift) == p) atomicAdd(&hist[(k >> shift) & (nb - 1)], 1u);
            }
            __syncthreads();
        }

        // per-chunk sums (8 bins each), then block-wide inclusive suffix scan
        unsigned s = 0;
        if (tid < nch) {
            int base = tid * 8;
            #pragma unroll
            for (int i = 0; i < 8; i++) s += hist[base + i];
        }
        sfx[tid] = s;
        __syncthreads();
        #pragma unroll
        for (int off = 1; off < 256; off <<= 1) {
            unsigned v = sfx[tid] + ((tid + off < 256) ? sfx[tid + off] : 0u);
            __syncthreads();
            sfx[tid] = v;
            __syncthreads();
        }
        if (tid < nch) {
            unsigned Saft = (tid + 1 < 256) ? sfx[tid + 1] : 0u;
            if (Saft < need && Saft + s >= need) {
                unsigned cum = Saft;
                int bb = tid * 8 + 7;
                while (cum + hist[bb] < need) { cum += hist[bb]; bb--; }
                sh_bin = (unsigned)bb;
                sh_need = need - cum;
            }
        }
        __syncthreads();
        unsigned bin = sh_bin;
        need = sh_need;
        if (lvl == 0)      p = bin;
        else if (lvl == 1) p = (p << 11) | bin;
        else               p = (p << 10) | bin;
        __syncthreads();
    }
    unsigned T = p;  // exact key of 392nd-largest non-positive

    for (int j = tid; j < CN_; j += 256) {
        unsigned k = keys[j];
        if (k >= T) atomicAdd(&cls[j >> 3], key_inv(k));
    }
    __syncthreads();
    if (tid == 0) cls[tgt] += s_pos;
    __syncthreads();

    float lsum = 0.f;
    for (int c = tid; c < C_; c += 256) {
        float l = cls[c];
        if (l != 0.0f) lsum += expf(l);
    }
    red[tid] = lsum;
    __syncthreads();
    for (int s2 = 128; s2 > 0; s2 >>= 1) {
        if (tid < s2) red[tid] += red[tid + s2];
        __syncthreads();
    }
    if (tid == 0) {
        float lt = cls[tgt];
        float num = (lt != 0.0f) ? expf(lt) : 0.0f;
        float pr = num / (1e-8f + red[0]);
        atomicAdd(&g_acc[0], (double)(-logf(pr + 1e-20f)));
    }
}

// ---------------- regularizer: per-row logsumexp over g_clog ----------------
__global__ void __launch_bounds__(256) lse_reg_kernel() {
    int row = blockIdx.x * 8 + (threadIdx.x >> 5);
    int lane = threadIdx.x & 31;
    const float* r = g_clog + (size_t)row * C_;

    float mx = -1e30f;
    for (int c = lane; c < C_; c += 32) mx = fmaxf(mx, r[c]);
    #pragma unroll
    for (int o = 16; o > 0; o >>= 1) mx = fmaxf(mx, __shfl_xor_sync(0xffffffffu, mx, o));

    float s = 0.f;
    for (int c = lane; c < C_; c += 32) s += expf(r[c] - mx);
    #pragma unroll
    for (int o = 16; o > 0; o >>= 1) s += __shfl_xor_sync(0xffffffffu, s, o);

    if (lane == 0) {
        int cl = row >> 3;
        float lse = mx + logf(s);
        atomicAdd(&g_acc[1], (double)(lse - r[cl]));
    }
}

// ---------------- finalize ---------------------------------------------------
__global__ void finalize_kernel(float* out, int out_size) {
    double lc = g_acc[0] / (double)B_;
    double rg = g_acc[1] / (double)CN_;
    out[0] = (float)(lc + WLAMBDA * rg);
    if (out_size > 1) out[1] = (float)lc;
}

// ---------------- launch -----------------------------------------------------
extern "C" void kernel_launch(void* const* d_in, const int* in_sizes, int n_in,
                              void* d_out, int out_size) {
    const float* x       = (const float*)d_in[0];
    const float* proxies = (const float*)d_in[1];
    const int*   target  = (const int*)d_in[2];
    float* out = (float*)d_out;

    cudaFuncSetAttribute(gemm_all, cudaFuncAttributeMaxDynamicSharedMemorySize, DYN_SMEM);

    prep_x<<<B_ / 16, 256>>>(x);
    prep_prox<<<CN_ / 32, 256>>>(proxies);
    gemm_all<<<1008, 256, DYN_SMEM>>>();
    topk_loss_kernel<<<B_, 256>>>(target);
    lse_reg_kernel<<<CN_ / 8, 256>>>();
    finalize_kernel<<<1, 1>>>(out, out_size);
}

// round 5
// speedup vs baseline: 3.4225x; 1.3603x over previous
#include <cuda_runtime.h>
#include <math.h>
#include <stdint.h>

// ---------------- problem constants ----------------------------------------
#define B_    1024
#define DIM_  512
#define C_    1000
#define N_    8
#define CN_   8000
#define CNP_  8064
#define CP_   1024
#define NEED_ 392       // topk(400) = 8 always-selected positives + top-392 others
#define WLAMBDA 0.3
#define CAP_  1024      // candidate buffer capacity

// ---------------- scratch (device globals) ----------------------------------
__device__ float4 g_xrA[(size_t)(B_ / 16) * 64 * 8 * 4];
__device__ float4 g_pTA[(size_t)(CNP_ / 16) * 64 * 8 * 4];
__device__ float4 g_pTB[(size_t)(CNP_ / 8) * 64 * 8 * 2];
__device__ float4 g_ccB[(size_t)(CP_ / 8) * 64 * 8 * 2];
__device__ float  g_sim[(size_t)B_ * CN_];
__device__ float  g_clog[(size_t)CN_ * C_];
__device__ double g_acc[2];

// ---------------- helpers ----------------------------------------------------
__device__ __forceinline__ float tf32r(float f) {
    uint32_t r;
    asm("cvt.rna.tf32.f32 %0, %1;" : "=r"(r) : "f"(f));
    return __uint_as_float(r);
}
__device__ __forceinline__ uint32_t smem_u32(const void* p) {
    uint32_t a;
    asm("{ .reg .u64 t; cvta.to.shared.u64 t, %1; cvt.u32.u64 %0, t; }" : "=r"(a) : "l"(p));
    return a;
}
__device__ __forceinline__ void cpa16(uint32_t dst, const void* src) {
    uint64_t g = __cvta_generic_to_global(src);
    asm volatile("cp.async.cg.shared.global [%0], [%1], 16;" :: "r"(dst), "l"(g));
}
#define CP_COMMIT() asm volatile("cp.async.commit_group;" ::: "memory")

__device__ __forceinline__ void mma_tf32(float* c, const uint32_t* a, const uint32_t* b) {
    asm volatile(
        "mma.sync.aligned.m16n8k8.row.col.f32.tf32.tf32.f32 "
        "{%0,%1,%2,%3}, {%4,%5,%6,%7}, {%8,%9}, {%0,%1,%2,%3};"
        : "+f"(c[0]), "+f"(c[1]), "+f"(c[2]), "+f"(c[3])
        : "r"(a[0]), "r"(a[1]), "r"(a[2]), "r"(a[3]), "r"(b[0]), "r"(b[1]));
}
__device__ __forceinline__ unsigned key_of(float v) {
    unsigned u = __float_as_uint(v);
    return (u & 0x80000000u) ? ~u : (u | 0x80000000u);
}
__device__ __forceinline__ float key_inv(unsigned k) {
    unsigned u = (k & 0x80000000u) ? (k & 0x7FFFFFFFu) : ~k;
    return __uint_as_float(u);
}

// ---------------- prep: x -> A-layout ----------------------------------------
__global__ void __launch_bounds__(256) prep_x(const float* __restrict__ x) {
    __shared__ float xs[16][516];
    int g = blockIdx.x, tid = threadIdx.x;
    if (g == 0 && tid < 2) g_acc[tid] = 0.0;

    const float4* x4 = (const float4*)x;
    #pragma unroll
    for (int e = 0; e < 8; e++) {
        int lin = e * 256 + tid;
        int row = lin >> 7, kf = lin & 127;
        float4 v = x4[(size_t)(g * 16 + row) * 128 + kf];
        xs[row][kf * 4 + 0] = v.x; xs[row][kf * 4 + 1] = v.y;
        xs[row][kf * 4 + 2] = v.z; xs[row][kf * 4 + 3] = v.w;
    }
    __syncthreads();
    #pragma unroll
    for (int e = 0; e < 8; e++) {
        int lin = e * 256 + tid;
        int ksG = lin >> 5, q = (lin >> 2) & 7, lc = lin & 3;
        int k = ksG * 8 + lc;
        float4 o;
        o.x = tf32r(xs[q][k]);     o.y = tf32r(xs[q + 8][k]);
        o.z = tf32r(xs[q][k + 4]); o.w = tf32r(xs[q + 8][k + 4]);
        g_xrA[((size_t)g * 64 + ksG) * 32 + q * 4 + lc] = o;
    }
}

// ---------------- prep: proxies -> norms, pTA, pTB, ccB ----------------------
__global__ void __launch_bounds__(256) prep_prox(const float* __restrict__ proxies) {
    __shared__ float red[8][32];
    __shared__ float sinv[32];
    int j0 = blockIdx.x * 32, tid = threadIdx.x;
    int jj = tid & 31, ds = tid >> 5;

    float acc = 0.f;
    for (int d = ds; d < DIM_; d += 8) {
        float v = proxies[(size_t)d * CN_ + j0 + jj];
        acc += v * v;
    }
    red[ds][jj] = acc;
    __syncthreads();
    if (ds == 0) {
        float s = 0.f;
        #pragma unroll
        for (int i = 0; i < 8; i++) s += red[i][jj];
        sinv[jj] = 1.0f / fmaxf(sqrtf(s), 1e-12f);
    }
    __syncthreads();

    #pragma unroll
    for (int e = 0; e < 16; e++) {
        int lin = e * 256 + tid;
        int gl = lin >> 11, ksG = (lin >> 5) & 63, q = (lin >> 2) & 7, lc = lin & 3;
        int jA = j0 + gl * 16 + q;
        int d = ksG * 8 + lc;
        float4 o;
        o.x = tf32r(proxies[(size_t)d * CN_ + jA] * sinv[jA - j0]);
        o.y = tf32r(proxies[(size_t)d * CN_ + jA + 8] * sinv[jA + 8 - j0]);
        o.z = tf32r(proxies[(size_t)(d + 4) * CN_ + jA] * sinv[jA - j0]);
        o.w = tf32r(proxies[(size_t)(d + 4) * CN_ + jA + 8] * sinv[jA + 8 - j0]);
        g_pTA[((size_t)(j0 / 16 + gl) * 64 + ksG) * 32 + q * 4 + lc] = o;
    }

    #pragma unroll
    for (int e = 0; e < 16; e++) {
        int lin = e * 256 + tid;
        int glB = lin >> 10, ksG = (lin >> 4) & 63, qB = (lin >> 1) & 7, p = lin & 1;
        int j = j0 + glB * 8 + qB;
        int k0 = ksG * 8 + 2 * p;
        float iv = sinv[j - j0];
        float4 o;
        o.x = tf32r(proxies[(size_t)k0 * CN_ + j] * iv);
        o.y = tf32r(proxies[(size_t)(k0 + 4) * CN_ + j] * iv);
        o.z = tf32r(proxies[(size_t)(k0 + 1) * CN_ + j] * iv);
        o.w = tf32r(proxies[(size_t)(k0 + 5) * CN_ + j] * iv);
        g_pTB[((size_t)(j0 / 8 + glB) * 64 + ksG) * 16 + qB * 2 + p] = o;
    }

    #pragma unroll
    for (int e = 0; e < 2; e++) {
        int lin = e * 256 + tid;
        int cl = lin >> 7, ksG = (lin >> 1) & 63, p = lin & 1;
        int c = j0 / 8 + cl;
        int gB = c >> 3, qB = c & 7;
        int k0 = ksG * 8 + 2 * p;
        float s0 = 0.f, s1 = 0.f, s2 = 0.f, s3 = 0.f;
        #pragma unroll
        for (int n = 0; n < 8; n++) {
            int j = c * 8 + n;
            float iv = sinv[j - j0];
            s0 += proxies[(size_t)k0 * CN_ + j] * iv;
            s1 += proxies[(size_t)(k0 + 4) * CN_ + j] * iv;
            s2 += proxies[(size_t)(k0 + 1) * CN_ + j] * iv;
            s3 += proxies[(size_t)(k0 + 5) * CN_ + j] * iv;
        }
        float4 o = make_float4(tf32r(s0), tf32r(s1), tf32r(s2), tf32r(s3));
        g_ccB[((size_t)gB * 64 + ksG) * 16 + qB * 2 + p] = o;
    }
}

// ---------------- merged tf32 mma.sync GEMM (3-stage, 2 CTA/SM) -------------
#define NCHUNK 16
#define STG 32768
#define DYN_SMEM (3 * STG)  // 98304

__global__ void __launch_bounds__(256, 2) gemm_all() {
    extern __shared__ char sh[];
    int bid = blockIdx.x;
    const float4 *Ag, *Bg;
    float* Cm;
    int bm, bn, Mrows, Ncols;
    if (bid < 504) {
        Ag = g_xrA; Bg = g_pTB; Cm = g_sim;
        bn = (bid % 63) * 128; bm = (bid / 63) * 128;
        Mrows = B_; Ncols = CN_;
    } else {
        int b2 = bid - 504;
        Ag = g_pTA; Bg = g_ccB; Cm = g_clog;
        bn = (b2 & 7) * 128; bm = (b2 >> 3) * 128;
        Mrows = CN_; Ncols = C_;
    }
    int tid = threadIdx.x, wid = tid >> 5, lane = tid & 31;
    int lr = lane >> 2, lc4 = lane & 3;
    uint32_t sb = smem_u32(sh);
    int GA0 = bm / 16, GB0 = bn / 8;

    auto load_stage = [&](int ch, int s) {
        uint32_t stage = sb + (uint32_t)s * STG;
        #pragma unroll
        for (int e = 0; e < 8; e++) {
            int lin = e * 256 + tid;
            if (lin < 1024) {
                int ks = lin >> 8, g = (lin >> 5) & 7, q = (lin >> 2) & 7, lc = lin & 3;
                cpa16(stage + (uint32_t)lin * 16,
                      Ag + ((size_t)(GA0 + g) * 64 + ch * 4 + ks) * 32 + q * 4 + lc);
            } else {
                int l2 = lin - 1024;
                int ks = l2 >> 8, gB = (l2 >> 4) & 15, qB = (l2 >> 1) & 7, p = l2 & 1;
                cpa16(stage + 16384u + (uint32_t)l2 * 16,
                      Bg + ((size_t)(GB0 + gB) * 64 + ch * 4 + ks) * 16 + qB * 2 + p);
            }
        }
        CP_COMMIT();
    };

    load_stage(0, 0);
    load_stage(1, 1);

    int ga = (wid >> 2) * 4;
    int gb = (wid & 3) * 4;

    float c[4][4][4];
    #pragma unroll
    for (int mt = 0; mt < 4; mt++)
        #pragma unroll
        for (int nt = 0; nt < 4; nt++)
            #pragma unroll
            for (int i = 0; i < 4; i++) c[mt][nt][i] = 0.f;

    for (int ch = 0; ch < NCHUNK; ch++) {
        if (ch < NCHUNK - 1) asm volatile("cp.async.wait_group 1;" ::: "memory");
        else                 asm volatile("cp.async.wait_group 0;" ::: "memory");
        __syncthreads();

        if (ch + 2 < NCHUNK) load_stage(ch + 2, (ch + 2) % 3);

        const float4* As = (const float4*)(sh + (ch % 3) * STG);
        const float2* Bs = (const float2*)(sh + (ch % 3) * STG + 16384);

        #pragma unroll
        for (int ks = 0; ks < 4; ks++) {
            uint32_t a[4][4], b[4][2];
            #pragma unroll
            for (int mt = 0; mt < 4; mt++) {
                float4 v = As[((ks * 8 + ga + mt) * 8 + lr) * 4 + lc4];
                a[mt][0] = __float_as_uint(v.x); a[mt][1] = __float_as_uint(v.y);
                a[mt][2] = __float_as_uint(v.z); a[mt][3] = __float_as_uint(v.w);
            }
            #pragma unroll
            for (int nt = 0; nt < 4; nt++) {
                float2 v = Bs[((ks * 16 + gb + nt) * 8 + lr) * 4 + lc4];
                b[nt][0] = __float_as_uint(v.x); b[nt][1] = __float_as_uint(v.y);
            }
            #pragma unroll
            for (int mt = 0; mt < 4; mt++)
                #pragma unroll
                for (int nt = 0; nt < 4; nt++)
                    mma_tf32(c[mt][nt], a[mt], b[nt]);
        }
    }

    int wm = (wid >> 2) * 64, wn = (wid & 3) * 32;
    #pragma unroll
    for (int mt = 0; mt < 4; mt++) {
        int row = bm + wm + mt * 16 + lr;
        #pragma unroll
        for (int nt = 0; nt < 4; nt++) {
            int col = bn + wn + nt * 8 + lc4 * 2;
            if (col < Ncols) {
                if (row < Mrows)
                    *(float2*)(Cm + (size_t)row * Ncols + col) = make_float2(c[mt][nt][0], c[mt][nt][1]);
                if (row + 8 < Mrows)
                    *(float2*)(Cm + (size_t)(row + 8) * Ncols + col) = make_float2(c[mt][nt][2], c[mt][nt][3]);
            }
        }
    }
}

// ---------------- merged epilogue: topk+loss (blocks 0..1023), lse (rest) ----
__global__ void __launch_bounds__(256) epilogue_kernel(const int* __restrict__ target) {
    __shared__ unsigned hist[2048];
    __shared__ unsigned cand[CAP_];
    __shared__ float    cls[C_];
    __shared__ unsigned uns[8];
    __shared__ float    wsum[8];
    __shared__ float    s_pos;
    __shared__ unsigned sh_bin, sh_need, sh_cnt;

    int tid = threadIdx.x;
    int wid = tid >> 5, lane = tid & 31;

    if (blockIdx.x >= B_) {
        // ---- regularizer logsumexp: 8 rows per block ----
        int row = (int)(blockIdx.x - B_) * 8 + wid;
        const float* r = g_clog + (size_t)row * C_;
        float mx = -1e30f;
        for (int c = lane; c < C_; c += 32) mx = fmaxf(mx, r[c]);
        #pragma unroll
        for (int o = 16; o > 0; o >>= 1) mx = fmaxf(mx, __shfl_xor_sync(0xffffffffu, mx, o));
        float s = 0.f;
        for (int c = lane; c < C_; c += 32) s += expf(r[c] - mx);
        #pragma unroll
        for (int o = 16; o > 0; o >>= 1) s += __shfl_xor_sync(0xffffffffu, s, o);
        if (lane == 0) {
            int cl = row >> 3;
            atomicAdd(&g_acc[1], (double)(mx + logf(s) - r[cl]));
        }
        return;
    }

    // ---- topk + classification loss, one row per block ----
    int b = blockIdx.x;
    const float4* row4 = (const float4*)(g_sim + (size_t)b * CN_);
    int tgt = target[b];

    for (int c = tid; c < C_; c += 256) cls[c] = 0.f;
    for (int i = tid; i < 2048; i += 256) hist[i] = 0;
    if (tid == 0) { s_pos = 0.f; sh_cnt = 0; }
    __syncthreads();

    // pass A: level-0 histogram (11-bit prefix) + positive sum
    float pos = 0.f;
    for (int i = tid; i < CN_ / 4; i += 256) {
        float4 v = row4[i];
        if ((i >> 1) == tgt) {
            pos += v.x + v.y + v.z + v.w;
        } else {
            atomicAdd(&hist[key_of(v.x) >> 21], 1u);
            atomicAdd(&hist[key_of(v.y) >> 21], 1u);
            atomicAdd(&hist[key_of(v.z) >> 21], 1u);
            atomicAdd(&hist[key_of(v.w) >> 21], 1u);
        }
    }
    if (pos != 0.f) atomicAdd(&s_pos, pos);
    __syncthreads();

    unsigned need = NEED_;

    // suffix-scan select over hist[nb] -> sh_bin, sh_need
    auto select_bin = [&](int nb, unsigned nd) {
        int nch = nb >> 3;
        unsigned chunk = 0;
        if (tid < nch) {
            int base = tid * 8;
            #pragma unroll
            for (int i = 0; i < 8; i++) chunk += hist[base + i];
        }
        unsigned v = chunk;
        #pragma unroll
        for (int off = 1; off < 32; off <<= 1) {
            unsigned t = __shfl_down_sync(0xffffffffu, v, off);
            if (lane + off < 32) v += t;
        }
        if (lane == 0) uns[wid] = v;
        __syncthreads();
        unsigned woff = 0;
        for (int w = wid + 1; w < 8; w++) woff += uns[w];
        unsigned Sincl = v + woff;
        unsigned Saft = Sincl - chunk;
        if (tid < nch && Saft < nd && Sincl >= nd) {
            unsigned cum = Saft;
            int bb = tid * 8 + 7;
            while (cum + hist[bb] < nd) { cum += hist[bb]; bb--; }
            sh_bin = (unsigned)bb;
            sh_need = nd - cum;
        }
        __syncthreads();
    };

    select_bin(2048, need);
    unsigned p0 = sh_bin;
    need = sh_need;
    __syncthreads();

    // collect candidates of the boundary bin
    for (int i = tid; i < CN_ / 4; i += 256) {
        if ((i >> 1) == tgt) continue;
        float4 v = row4[i];
        unsigned k;
        k = key_of(v.x); if ((k >> 21) == p0) { unsigned q = atomicAdd(&sh_cnt, 1u); if (q < CAP_) cand[q] = k; }
        k = key_of(v.y); if ((k >> 21) == p0) { unsigned q = atomicAdd(&sh_cnt, 1u); if (q < CAP_) cand[q] = k; }
        k = key_of(v.z); if ((k >> 21) == p0) { unsigned q = atomicAdd(&sh_cnt, 1u); if (q < CAP_) cand[q] = k; }
        k = key_of(v.w); if ((k >> 21) == p0) { unsigned q = atomicAdd(&sh_cnt, 1u); if (q < CAP_) cand[q] = k; }
    }
    __syncthreads();
    unsigned cnt = sh_cnt;
    bool small = (cnt <= CAP_);

    // level 1: bins on bits [20:10]
    for (int i = tid; i < 2048; i += 256) hist[i] = 0;
    __syncthreads();
    if (small) {
        for (unsigned i = tid; i < cnt; i += 256)
            atomicAdd(&hist[(cand[i] >> 10) & 2047u], 1u);
    } else {
        for (int i = tid; i < CN_ / 4; i += 256) {
            if ((i >> 1) == tgt) continue;
            float4 v = row4[i];
            unsigned k;
            k = key_of(v.x); if ((k >> 21) == p0) atomicAdd(&hist[(k >> 10) & 2047u], 1u);
            k = key_of(v.y); if ((k >> 21) == p0) atomicAdd(&hist[(k >> 10) & 2047u], 1u);
            k = key_of(v.z); if ((k >> 21) == p0) atomicAdd(&hist[(k >> 10) & 2047u], 1u);
            k = key_of(v.w); if ((k >> 21) == p0) atomicAdd(&hist[(k >> 10) & 2047u], 1u);
        }
    }
    __syncthreads();
    select_bin(2048, need);
    unsigned p1 = (p0 << 11) | sh_bin;   // 22-bit prefix of (k >> 10)
    need = sh_need;
    __syncthreads();

    // level 2: bins on bits [9:0]
    for (int i = tid; i < 1024; i += 256) hist[i] = 0;
    __syncthreads();
    if (small) {
        for (unsigned i = tid; i < cnt; i += 256) {
            unsigned k = cand[i];
            if ((k >> 10) == p1) atomicAdd(&hist[k & 1023u], 1u);
        }
    } else {
        for (int i = tid; i < CN_ / 4; i += 256) {
            if ((i >> 1) == tgt) continue;
            float4 v = row4[i];
            unsigned k;
            k = key_of(v.x); if ((k >> 10) == p1) atomicAdd(&hist[k & 1023u], 1u);
            k = key_of(v.y); if ((k >> 10) == p1) atomicAdd(&hist[k & 1023u], 1u);
            k = key_of(v.z); if ((k >> 10) == p1) atomicAdd(&hist[k & 1023u], 1u);
            k = key_of(v.w); if ((k >> 10) == p1) atomicAdd(&hist[k & 1023u], 1u);
        }
    }
    __syncthreads();
    select_bin(1024, need);
    unsigned T = (p1 << 10) | sh_bin;    // exact key of the 392nd-largest non-positive
    __syncthreads();

    // final accumulate into class buckets
    for (int i = tid; i < CN_ / 4; i += 256) {
        if ((i >> 1) == tgt) continue;
        float4 v = row4[i];
        float add = 0.f;
        if (key_of(v.x) >= T) add += v.x;
        if (key_of(v.y) >= T) add += v.y;
        if (key_of(v.z) >= T) add += v.z;
        if (key_of(v.w) >= T) add += v.w;
        if (add != 0.f) atomicAdd(&cls[i >> 1], add);
    }
    __syncthreads();
    if (tid == 0) cls[tgt] += s_pos;
    __syncthreads();

    // masked softmax loss
    float lsum = 0.f;
    for (int c = tid; c < C_; c += 256) {
        float l = cls[c];
        if (l != 0.0f) lsum += expf(l);
    }
    #pragma unroll
    for (int o = 16; o > 0; o >>= 1) lsum += __shfl_xor_sync(0xffffffffu, lsum, o);
    if (lane == 0) wsum[wid] = lsum;
    __syncthreads();
    if (tid == 0) {
        float tot = 0.f;
        #pragma unroll
        for (int w = 0; w < 8; w++) tot += wsum[w];
        float lt = cls[tgt];
        float num = (lt != 0.0f) ? expf(lt) : 0.0f;
        float pr = num / (1e-8f + tot);
        atomicAdd(&g_acc[0], (double)(-logf(pr + 1e-20f)));
    }
}

// ---------------- finalize ---------------------------------------------------
__global__ void finalize_kernel(float* out, int out_size) {
    double lc = g_acc[0] / (double)B_;
    double rg = g_acc[1] / (double)CN_;
    out[0] = (float)(lc + WLAMBDA * rg);
    if (out_size > 1) out[1] = (float)lc;
}

// ---------------- launch -----------------------------------------------------
extern "C" void kernel_launch(void* const* d_in, const int* in_sizes, int n_in,
                              void* d_out, int out_size) {
    const float* x       = (const float*)d_in[0];
    const float* proxies = (const float*)d_in[1];
    const int*   target  = (const int*)d_in[2];
    float* out = (float*)d_out;

    cudaFuncSetAttribute(gemm_all, cudaFuncAttributeMaxDynamicSharedMemorySize, DYN_SMEM);

    prep_x<<<B_ / 16, 256>>>(x);
    prep_prox<<<CN_ / 32, 256>>>(proxies);
    gemm_all<<<1008, 256, DYN_SMEM>>>();
    epilogue_kernel<<<B_ + CN_ / 8, 256>>>(target);
    finalize_kernel<<<1, 1>>>(out, out_size);
}